// round 3
// baseline (speedup 1.0000x reference)
#include <cuda_runtime.h>
#include <math.h>

// ---------------------------------------------------------------------------
// MultiheadDiffAttn  (B=2, N=2048, E=1024, H=8, D=64, depth=12)
//
//   q = (x@Wq)*D^-0.5 -> [b,16,n,64]      k = x@Wk -> [b,16,n,64]
//   v = x@Wv -> [b,8,n,128]
//   s_hh = q_hh @ k_hh^T   (hh = 0..15)   softmax rows
//   w_h  = p_{2h} - lam * p_{2h+1}
//   o_h  = w_h @ v_h   -> per-head LayerNorm(128) * g + b
//   out  = concat_h(o) @ Wo
// ---------------------------------------------------------------------------

#define Bb   2
#define Nq   2048
#define Ee   1024
#define Hh   8
#define HH2  16
#define Dd   64
#define DV   128

// scratch (allocation-free: __device__ globals)
__device__ float g_q[Bb * HH2 * Nq * Dd];          // [b,hh,n,d]   16 MB
__device__ float g_k[Bb * HH2 * Nq * Dd];          // 16 MB
__device__ float g_v[Bb * Hh * Nq * DV];           // 16 MB
__device__ float g_o[Bb * Nq * Ee];                // post-LN, [b,n,e] 16 MB
__device__ float g_S[(size_t)Bb * HH2 * Nq * Nq];  // scores, 512 MB
__device__ float g_lambda;

// ---------------------------------------------------------------------------
__global__ void lambda_kernel(const float* lq1, const float* lk1,
                              const float* lq2, const float* lk2) {
    int t = threadIdx.x;  // 32 threads
    float s1 = lq1[t] * lk1[t] + lq1[t + 32] * lk1[t + 32];
    float s2 = lq2[t] * lk2[t] + lq2[t + 32] * lk2[t + 32];
    #pragma unroll
    for (int o = 16; o; o >>= 1) {
        s1 += __shfl_xor_sync(0xFFFFFFFFu, s1, o);
        s2 += __shfl_xor_sync(0xFFFFFFFFu, s2, o);
    }
    if (t == 0) {
        float lam_init = 0.8f - 0.6f * expf(-0.3f * 12.0f);
        g_lambda = expf(s1) - expf(s2) + lam_init;
    }
}

// ---------------------------------------------------------------------------
// Generic 128x128x16 fp32 SGEMM, M=4096 N=1024 K=1024, 256 threads, 8x8/thread.
// MODE 0: C = g_o @ B  -> C (plain)          (final projection)
// MODE 1: C = A  @ B  -> g_q  scattered, *0.125
// MODE 2: C = A  @ B  -> g_k  scattered
// MODE 3: C = A  @ B  -> g_v  scattered
template <int MODE>
__global__ void __launch_bounds__(256)
sgemm_nn_kernel(const float* __restrict__ A, const float* __restrict__ B,
                float* __restrict__ C) {
    const int Kk = 1024, Nn = 1024;
    __shared__ float As[16][132];   // transposed: As[k][m]
    __shared__ float Bs[16][128];   // Bs[k][n]

    const float* Ap = (MODE == 0) ? g_o : A;

    int tid = threadIdx.x;
    int tx = tid & 15, ty = tid >> 4;
    int m0 = blockIdx.y * 128, n0 = blockIdx.x * 128;
    int arow = tid >> 2, akv = (tid & 3) * 4;
    int brow = tid >> 5, bcol = (tid & 31) * 4;

    float acc[8][8];
    #pragma unroll
    for (int i = 0; i < 8; i++)
        #pragma unroll
        for (int j = 0; j < 8; j++) acc[i][j] = 0.f;

    for (int k0 = 0; k0 < Kk; k0 += 16) {
        #pragma unroll
        for (int hh = 0; hh < 2; hh++) {
            float4 av = *(const float4*)&Ap[(size_t)(m0 + arow + hh * 64) * Kk + k0 + akv];
            As[akv + 0][arow + hh * 64] = av.x;
            As[akv + 1][arow + hh * 64] = av.y;
            As[akv + 2][arow + hh * 64] = av.z;
            As[akv + 3][arow + hh * 64] = av.w;
        }
        #pragma unroll
        for (int hh = 0; hh < 2; hh++) {
            float4 bv = *(const float4*)&B[(size_t)(k0 + brow + hh * 8) * Nn + n0 + bcol];
            *(float4*)&Bs[brow + hh * 8][bcol] = bv;
        }
        __syncthreads();
        #pragma unroll
        for (int kk = 0; kk < 16; kk++) {
            float a[8], b[8];
            *(float4*)&a[0] = *(float4*)&As[kk][ty * 8];
            *(float4*)&a[4] = *(float4*)&As[kk][ty * 8 + 4];
            *(float4*)&b[0] = *(float4*)&Bs[kk][tx * 8];
            *(float4*)&b[4] = *(float4*)&Bs[kk][tx * 8 + 4];
            #pragma unroll
            for (int i = 0; i < 8; i++)
                #pragma unroll
                for (int j = 0; j < 8; j++) acc[i][j] += a[i] * b[j];
        }
        __syncthreads();
    }

    #pragma unroll
    for (int i = 0; i < 8; i++) {
        int row = m0 + ty * 8 + i;
        int bb = row >> 11, nn2 = row & 2047;
        #pragma unroll
        for (int j = 0; j < 8; j++) {
            int col = n0 + tx * 8 + j;
            float v = acc[i][j];
            if (MODE == 0) {
                C[(size_t)row * 1024 + col] = v;
            } else if (MODE == 1) {
                int hh = col >> 6, d = col & 63;
                g_q[((size_t)((bb * 16 + hh) * 2048 + nn2)) * 64 + d] = v * 0.125f;
            } else if (MODE == 2) {
                int hh = col >> 6, d = col & 63;
                g_k[((size_t)((bb * 16 + hh) * 2048 + nn2)) * 64 + d] = v;
            } else {
                int h = col >> 7, c = col & 127;
                g_v[((size_t)((bb * 8 + h) * 2048 + nn2)) * 128 + c] = v;
            }
        }
    }
}

// ---------------------------------------------------------------------------
// Scores: S[z] = Q[z] @ K[z]^T, z = b*16+hh, 2048x2048x64. NT GEMM, 128x128 tile.
__global__ void __launch_bounds__(256)
scores_kernel() {
    const float* A  = g_q + (size_t)blockIdx.z * Nq * Dd;
    const float* Bm = g_k + (size_t)blockIdx.z * Nq * Dd;
    float* C = g_S + (size_t)blockIdx.z * Nq * Nq;

    __shared__ float As[16][132];
    __shared__ float Bs[16][132];

    int tid = threadIdx.x;
    int tx = tid & 15, ty = tid >> 4;
    int m0 = blockIdx.y * 128, n0 = blockIdx.x * 128;
    int arow = tid >> 2, akv = (tid & 3) * 4;

    float acc[8][8];
    #pragma unroll
    for (int i = 0; i < 8; i++)
        #pragma unroll
        for (int j = 0; j < 8; j++) acc[i][j] = 0.f;

    for (int k0 = 0; k0 < 64; k0 += 16) {
        #pragma unroll
        for (int hh = 0; hh < 2; hh++) {
            float4 av = *(const float4*)&A[(size_t)(m0 + arow + hh * 64) * 64 + k0 + akv];
            As[akv + 0][arow + hh * 64] = av.x;
            As[akv + 1][arow + hh * 64] = av.y;
            As[akv + 2][arow + hh * 64] = av.z;
            As[akv + 3][arow + hh * 64] = av.w;
            float4 bv = *(const float4*)&Bm[(size_t)(n0 + arow + hh * 64) * 64 + k0 + akv];
            Bs[akv + 0][arow + hh * 64] = bv.x;
            Bs[akv + 1][arow + hh * 64] = bv.y;
            Bs[akv + 2][arow + hh * 64] = bv.z;
            Bs[akv + 3][arow + hh * 64] = bv.w;
        }
        __syncthreads();
        #pragma unroll
        for (int kk = 0; kk < 16; kk++) {
            float a[8], b[8];
            *(float4*)&a[0] = *(float4*)&As[kk][ty * 8];
            *(float4*)&a[4] = *(float4*)&As[kk][ty * 8 + 4];
            *(float4*)&b[0] = *(float4*)&Bs[kk][tx * 8];
            *(float4*)&b[4] = *(float4*)&Bs[kk][tx * 8 + 4];
            #pragma unroll
            for (int i = 0; i < 8; i++)
                #pragma unroll
                for (int j = 0; j < 8; j++) acc[i][j] += a[i] * b[j];
        }
        __syncthreads();
    }

    #pragma unroll
    for (int i = 0; i < 8; i++)
        #pragma unroll
        for (int j = 0; j < 8; j++)
            C[(size_t)(m0 + ty * 8 + i) * 2048 + (n0 + tx * 8 + j)] = acc[i][j];
}

// ---------------------------------------------------------------------------
// Softmax both streams of one head pair for one query row; combine in place:
//   g_S[2h-slab] <- softmax(s1) - lam * softmax(s2)
__global__ void __launch_bounds__(256)
softmax_kernel() {
    int q = blockIdx.x, h = blockIdx.y, b = blockIdx.z;
    float lam = g_lambda;
    float* s1 = g_S + ((size_t)(b * 16 + 2 * h)) * Nq * Nq + (size_t)q * Nq;
    float* s2 = s1 + (size_t)Nq * Nq;

    int tid = threadIdx.x;  // 256
    float v1[8], v2[8];
    float m1 = -1e30f, m2 = -1e30f;
    #pragma unroll
    for (int i = 0; i < 8; i++) {
        v1[i] = s1[tid + i * 256];
        v2[i] = s2[tid + i * 256];
        m1 = fmaxf(m1, v1[i]);
        m2 = fmaxf(m2, v2[i]);
    }
    __shared__ float red1[8], red2[8], sum1[8], sum2[8];
    #pragma unroll
    for (int o = 16; o; o >>= 1) {
        m1 = fmaxf(m1, __shfl_xor_sync(0xFFFFFFFFu, m1, o));
        m2 = fmaxf(m2, __shfl_xor_sync(0xFFFFFFFFu, m2, o));
    }
    int warp = tid >> 5, lane = tid & 31;
    if (lane == 0) { red1[warp] = m1; red2[warp] = m2; }
    __syncthreads();
    m1 = red1[0]; m2 = red2[0];
    #pragma unroll
    for (int w = 1; w < 8; w++) {
        m1 = fmaxf(m1, red1[w]);
        m2 = fmaxf(m2, red2[w]);
    }
    float l1 = 0.f, l2 = 0.f;
    #pragma unroll
    for (int i = 0; i < 8; i++) {
        v1[i] = expf(v1[i] - m1); l1 += v1[i];
        v2[i] = expf(v2[i] - m2); l2 += v2[i];
    }
    #pragma unroll
    for (int o = 16; o; o >>= 1) {
        l1 += __shfl_xor_sync(0xFFFFFFFFu, l1, o);
        l2 += __shfl_xor_sync(0xFFFFFFFFu, l2, o);
    }
    if (lane == 0) { sum1[warp] = l1; sum2[warp] = l2; }
    __syncthreads();
    l1 = sum1[0]; l2 = sum2[0];
    #pragma unroll
    for (int w = 1; w < 8; w++) { l1 += sum1[w]; l2 += sum2[w]; }
    float inv1 = 1.f / l1, inv2 = lam / l2;
    #pragma unroll
    for (int i = 0; i < 8; i++)
        s1[tid + i * 256] = v1[i] * inv1 - v2[i] * inv2;
}

// ---------------------------------------------------------------------------
// O = W @ V per (b,h): 2048x128x2048; BN=128 covers all channels -> LN fused.
__global__ void __launch_bounds__(256)
ov_ln_kernel(const float* __restrict__ lng, const float* __restrict__ lnb) {
    int z = blockIdx.z;          // b*8 + h
    int b = z >> 3, h = z & 7;
    const float* A  = g_S + ((size_t)(b * 16 + 2 * h)) * Nq * Nq;  // combined W
    const float* Bm = g_v + (size_t)z * Nq * DV;

    extern __shared__ float sm[];
    float (*As)[132] = (float(*)[132])sm;                       // 16*132
    float (*Bs)[128] = (float(*)[128])(sm + 16 * 132);          // 16*128
    float (*Os)[132] = (float(*)[132])(sm + 16 * 132 + 16 * 128);  // 128*132

    int tid = threadIdx.x;
    int tx = tid & 15, ty = tid >> 4;
    int m0 = blockIdx.y * 128;
    int arow = tid >> 2, akv = (tid & 3) * 4;
    int brow = tid >> 5, bcol = (tid & 31) * 4;

    float acc[8][8];
    #pragma unroll
    for (int i = 0; i < 8; i++)
        #pragma unroll
        for (int j = 0; j < 8; j++) acc[i][j] = 0.f;

    for (int k0 = 0; k0 < 2048; k0 += 16) {
        #pragma unroll
        for (int hh = 0; hh < 2; hh++) {
            float4 av = *(const float4*)&A[(size_t)(m0 + arow + hh * 64) * 2048 + k0 + akv];
            As[akv + 0][arow + hh * 64] = av.x;
            As[akv + 1][arow + hh * 64] = av.y;
            As[akv + 2][arow + hh * 64] = av.z;
            As[akv + 3][arow + hh * 64] = av.w;
        }
        #pragma unroll
        for (int hh = 0; hh < 2; hh++) {
            float4 bv = *(const float4*)&Bm[(size_t)(k0 + brow + hh * 8) * 128 + bcol];
            *(float4*)&Bs[brow + hh * 8][bcol] = bv;
        }
        __syncthreads();
        #pragma unroll
        for (int kk = 0; kk < 16; kk++) {
            float a[8], bfr[8];
            *(float4*)&a[0] = *(float4*)&As[kk][ty * 8];
            *(float4*)&a[4] = *(float4*)&As[kk][ty * 8 + 4];
            *(float4*)&bfr[0] = *(float4*)&Bs[kk][tx * 8];
            *(float4*)&bfr[4] = *(float4*)&Bs[kk][tx * 8 + 4];
            #pragma unroll
            for (int i = 0; i < 8; i++)
                #pragma unroll
                for (int j = 0; j < 8; j++) acc[i][j] += a[i] * bfr[j];
        }
        __syncthreads();
    }

    #pragma unroll
    for (int i = 0; i < 8; i++)
        #pragma unroll
        for (int j = 0; j < 8; j++) Os[ty * 8 + i][tx * 8 + j] = acc[i][j];
    __syncthreads();

    int warp = tid >> 5, lane = tid & 31;
    for (int r0 = 0; r0 < 16; r0++) {
        int r = warp * 16 + r0;
        float s = 0.f, ss = 0.f;
        float vals[4];
        #pragma unroll
        for (int j = 0; j < 4; j++) {
            vals[j] = Os[r][lane + 32 * j];
            s  += vals[j];
            ss += vals[j] * vals[j];
        }
        #pragma unroll
        for (int o = 16; o; o >>= 1) {
            s  += __shfl_xor_sync(0xFFFFFFFFu, s, o);
            ss += __shfl_xor_sync(0xFFFFFFFFu, ss, o);
        }
        float mean = s * (1.f / 128.f);
        float var  = ss * (1.f / 128.f) - mean * mean;
        float rstd = rsqrtf(var + 1e-5f);
        int qrow = m0 + r;
        float* dst = g_o + ((size_t)(b * 2048 + qrow)) * 1024 + h * 128;
        #pragma unroll
        for (int j = 0; j < 4; j++) {
            int c = lane + 32 * j;
            dst[c] = (vals[j] - mean) * rstd * lng[c] + lnb[c];
        }
    }
}

// ---------------------------------------------------------------------------
extern "C" void kernel_launch(void* const* d_in, const int* in_sizes, int n_in,
                              void* d_out, int out_size) {
    const float* x   = (const float*)d_in[0];
    const float* Wq  = (const float*)d_in[1];
    const float* Wk  = (const float*)d_in[2];
    const float* Wv  = (const float*)d_in[3];
    const float* Wo  = (const float*)d_in[4];
    const float* lq1 = (const float*)d_in[5];
    const float* lk1 = (const float*)d_in[6];
    const float* lq2 = (const float*)d_in[7];
    const float* lk2 = (const float*)d_in[8];
    const float* lng = (const float*)d_in[9];
    const float* lnb = (const float*)d_in[10];
    float* out = (float*)d_out;

    lambda_kernel<<<1, 32>>>(lq1, lk1, lq2, lk2);

    dim3 gproj(1024 / 128, 4096 / 128);  // (8, 32)
    sgemm_nn_kernel<1><<<gproj, 256>>>(x, Wq, nullptr);
    sgemm_nn_kernel<2><<<gproj, 256>>>(x, Wk, nullptr);
    sgemm_nn_kernel<3><<<gproj, 256>>>(x, Wv, nullptr);

    scores_kernel<<<dim3(16, 16, 32), 256>>>();
    softmax_kernel<<<dim3(2048, 8, 2), 256>>>();

    const int smem_ov = (16 * 132 + 16 * 128 + 128 * 132) * 4;  // 84224 B
    cudaFuncSetAttribute(ov_ln_kernel, cudaFuncAttributeMaxDynamicSharedMemorySize, smem_ov);
    ov_ln_kernel<<<dim3(1, 16, 16), 256, smem_ov>>>(lng, lnb);

    sgemm_nn_kernel<0><<<gproj, 256>>>(nullptr, Wo, out);
}

// round 4
// speedup vs baseline: 1.0035x; 1.0035x over previous
#include <cuda_runtime.h>
#include <math.h>

// ---------------------------------------------------------------------------
// MultiheadDiffAttn  (B=2, N=2048, E=1024, H=8, D=64, depth=12)
//
//   q = (x@Wq)*D^-0.5 -> [b,16,n,64]      k = x@Wk -> [b,16,n,64]
//   v = x@Wv -> [b,8,n,128]
//   s_hh = q_hh @ k_hh^T   (hh = 0..15)   softmax rows
//   w_h  = p_{2h} - lam * p_{2h+1}
//   o_h  = w_h @ v_h   -> per-head LayerNorm(128) * g + b
//   out  = concat_h(o) @ Wo
// ---------------------------------------------------------------------------

#define Bb   2
#define Nq   2048
#define Ee   1024
#define Hh   8
#define HH2  16
#define Dd   64
#define DV   128

// scratch (allocation-free: __device__ globals)
__device__ float g_q[Bb * HH2 * Nq * Dd];          // [b,hh,n,d]   16 MB
__device__ float g_k[Bb * HH2 * Nq * Dd];          // 16 MB
__device__ float g_v[Bb * Hh * Nq * DV];           // 16 MB
__device__ float g_o[Bb * Nq * Ee];                // post-LN, [b,n,e] 16 MB
__device__ float g_S[(size_t)Bb * HH2 * Nq * Nq];  // scores, 512 MB
__device__ float g_lambda;

// ---------------------------------------------------------------------------
__global__ void lambda_kernel(const float* lq1, const float* lk1,
                              const float* lq2, const float* lk2) {
    int t = threadIdx.x;  // 32 threads
    float s1 = lq1[t] * lk1[t] + lq1[t + 32] * lk1[t + 32];
    float s2 = lq2[t] * lk2[t] + lq2[t + 32] * lk2[t + 32];
    #pragma unroll
    for (int o = 16; o; o >>= 1) {
        s1 += __shfl_xor_sync(0xFFFFFFFFu, s1, o);
        s2 += __shfl_xor_sync(0xFFFFFFFFu, s2, o);
    }
    if (t == 0) {
        float lam_init = 0.8f - 0.6f * expf(-0.3f * 12.0f);
        g_lambda = expf(s1) - expf(s2) + lam_init;
    }
}

// ---------------------------------------------------------------------------
// Generic 128x128x16 fp32 SGEMM, M=4096 N=1024 K=1024, 256 threads, 8x8/thread.
// MODE 0: C = g_o @ B  -> C (plain)          (final projection)
// MODE 1: C = A  @ B  -> g_q  scattered, *0.125
// MODE 2: C = A  @ B  -> g_k  scattered
// MODE 3: C = A  @ B  -> g_v  scattered
template <int MODE>
__global__ void __launch_bounds__(256)
sgemm_nn_kernel(const float* __restrict__ A, const float* __restrict__ B,
                float* __restrict__ C) {
    const int Kk = 1024, Nn = 1024;
    __shared__ float As[16][132];   // transposed: As[k][m]
    __shared__ float Bs[16][128];   // Bs[k][n]

    const float* Ap = (MODE == 0) ? g_o : A;

    int tid = threadIdx.x;
    int tx = tid & 15, ty = tid >> 4;
    int m0 = blockIdx.y * 128, n0 = blockIdx.x * 128;
    int arow = tid >> 2, akv = (tid & 3) * 4;
    int brow = tid >> 5, bcol = (tid & 31) * 4;

    float acc[8][8];
    #pragma unroll
    for (int i = 0; i < 8; i++)
        #pragma unroll
        for (int j = 0; j < 8; j++) acc[i][j] = 0.f;

    for (int k0 = 0; k0 < Kk; k0 += 16) {
        #pragma unroll
        for (int hh = 0; hh < 2; hh++) {
            float4 av = *(const float4*)&Ap[(size_t)(m0 + arow + hh * 64) * Kk + k0 + akv];
            As[akv + 0][arow + hh * 64] = av.x;
            As[akv + 1][arow + hh * 64] = av.y;
            As[akv + 2][arow + hh * 64] = av.z;
            As[akv + 3][arow + hh * 64] = av.w;
        }
        #pragma unroll
        for (int hh = 0; hh < 2; hh++) {
            float4 bv = *(const float4*)&B[(size_t)(k0 + brow + hh * 8) * Nn + n0 + bcol];
            *(float4*)&Bs[brow + hh * 8][bcol] = bv;
        }
        __syncthreads();
        #pragma unroll
        for (int kk = 0; kk < 16; kk++) {
            float a[8], b[8];
            *(float4*)&a[0] = *(float4*)&As[kk][ty * 8];
            *(float4*)&a[4] = *(float4*)&As[kk][ty * 8 + 4];
            *(float4*)&b[0] = *(float4*)&Bs[kk][tx * 8];
            *(float4*)&b[4] = *(float4*)&Bs[kk][tx * 8 + 4];
            #pragma unroll
            for (int i = 0; i < 8; i++)
                #pragma unroll
                for (int j = 0; j < 8; j++) acc[i][j] += a[i] * b[j];
        }
        __syncthreads();
    }

    #pragma unroll
    for (int i = 0; i < 8; i++) {
        int row = m0 + ty * 8 + i;
        int bb = row >> 11, nn2 = row & 2047;
        #pragma unroll
        for (int j = 0; j < 8; j++) {
            int col = n0 + tx * 8 + j;
            float v = acc[i][j];
            if (MODE == 0) {
                C[(size_t)row * 1024 + col] = v;
            } else if (MODE == 1) {
                int hh = col >> 6, d = col & 63;
                g_q[((size_t)((bb * 16 + hh) * 2048 + nn2)) * 64 + d] = v * 0.125f;
            } else if (MODE == 2) {
                int hh = col >> 6, d = col & 63;
                g_k[((size_t)((bb * 16 + hh) * 2048 + nn2)) * 64 + d] = v;
            } else {
                int h = col >> 7, c = col & 127;
                g_v[((size_t)((bb * 8 + h) * 2048 + nn2)) * 128 + c] = v;
            }
        }
    }
}

// ---------------------------------------------------------------------------
// Scores: S[z] = Q[z] @ K[z]^T, z = b*16+hh, 2048x2048x64. NT GEMM, 128x128 tile.
__global__ void __launch_bounds__(256)
scores_kernel() {
    const float* A  = g_q + (size_t)blockIdx.z * Nq * Dd;
    const float* Bm = g_k + (size_t)blockIdx.z * Nq * Dd;
    float* C = g_S + (size_t)blockIdx.z * Nq * Nq;

    __shared__ float As[16][132];
    __shared__ float Bs[16][132];

    int tid = threadIdx.x;
    int tx = tid & 15, ty = tid >> 4;
    int m0 = blockIdx.y * 128, n0 = blockIdx.x * 128;
    int arow = tid >> 2, akv = (tid & 3) * 4;

    float acc[8][8];
    #pragma unroll
    for (int i = 0; i < 8; i++)
        #pragma unroll
        for (int j = 0; j < 8; j++) acc[i][j] = 0.f;

    for (int k0 = 0; k0 < 64; k0 += 16) {
        #pragma unroll
        for (int hh = 0; hh < 2; hh++) {
            float4 av = *(const float4*)&A[(size_t)(m0 + arow + hh * 64) * 64 + k0 + akv];
            As[akv + 0][arow + hh * 64] = av.x;
            As[akv + 1][arow + hh * 64] = av.y;
            As[akv + 2][arow + hh * 64] = av.z;
            As[akv + 3][arow + hh * 64] = av.w;
            float4 bv = *(const float4*)&Bm[(size_t)(n0 + arow + hh * 64) * 64 + k0 + akv];
            Bs[akv + 0][arow + hh * 64] = bv.x;
            Bs[akv + 1][arow + hh * 64] = bv.y;
            Bs[akv + 2][arow + hh * 64] = bv.z;
            Bs[akv + 3][arow + hh * 64] = bv.w;
        }
        __syncthreads();
        #pragma unroll
        for (int kk = 0; kk < 16; kk++) {
            float a[8], b[8];
            *(float4*)&a[0] = *(float4*)&As[kk][ty * 8];
            *(float4*)&a[4] = *(float4*)&As[kk][ty * 8 + 4];
            *(float4*)&b[0] = *(float4*)&Bs[kk][tx * 8];
            *(float4*)&b[4] = *(float4*)&Bs[kk][tx * 8 + 4];
            #pragma unroll
            for (int i = 0; i < 8; i++)
                #pragma unroll
                for (int j = 0; j < 8; j++) acc[i][j] += a[i] * b[j];
        }
        __syncthreads();
    }

    #pragma unroll
    for (int i = 0; i < 8; i++)
        #pragma unroll
        for (int j = 0; j < 8; j++)
            C[(size_t)(m0 + ty * 8 + i) * 2048 + (n0 + tx * 8 + j)] = acc[i][j];
}

// ---------------------------------------------------------------------------
// Softmax both streams of one head pair for one query row; combine in place:
//   g_S[2h-slab] <- softmax(s1) - lam * softmax(s2)
__global__ void __launch_bounds__(256)
softmax_kernel() {
    int q = blockIdx.x, h = blockIdx.y, b = blockIdx.z;
    float lam = g_lambda;
    float* s1 = g_S + ((size_t)(b * 16 + 2 * h)) * Nq * Nq + (size_t)q * Nq;
    float* s2 = s1 + (size_t)Nq * Nq;

    int tid = threadIdx.x;  // 256
    float v1[8], v2[8];
    float m1 = -1e30f, m2 = -1e30f;
    #pragma unroll
    for (int i = 0; i < 8; i++) {
        v1[i] = s1[tid + i * 256];
        v2[i] = s2[tid + i * 256];
        m1 = fmaxf(m1, v1[i]);
        m2 = fmaxf(m2, v2[i]);
    }
    __shared__ float red1[8], red2[8], sum1[8], sum2[8];
    #pragma unroll
    for (int o = 16; o; o >>= 1) {
        m1 = fmaxf(m1, __shfl_xor_sync(0xFFFFFFFFu, m1, o));
        m2 = fmaxf(m2, __shfl_xor_sync(0xFFFFFFFFu, m2, o));
    }
    int warp = tid >> 5, lane = tid & 31;
    if (lane == 0) { red1[warp] = m1; red2[warp] = m2; }
    __syncthreads();
    m1 = red1[0]; m2 = red2[0];
    #pragma unroll
    for (int w = 1; w < 8; w++) {
        m1 = fmaxf(m1, red1[w]);
        m2 = fmaxf(m2, red2[w]);
    }
    float l1 = 0.f, l2 = 0.f;
    #pragma unroll
    for (int i = 0; i < 8; i++) {
        v1[i] = expf(v1[i] - m1); l1 += v1[i];
        v2[i] = expf(v2[i] - m2); l2 += v2[i];
    }
    #pragma unroll
    for (int o = 16; o; o >>= 1) {
        l1 += __shfl_xor_sync(0xFFFFFFFFu, l1, o);
        l2 += __shfl_xor_sync(0xFFFFFFFFu, l2, o);
    }
    if (lane == 0) { sum1[warp] = l1; sum2[warp] = l2; }
    __syncthreads();
    l1 = sum1[0]; l2 = sum2[0];
    #pragma unroll
    for (int w = 1; w < 8; w++) { l1 += sum1[w]; l2 += sum2[w]; }
    float inv1 = 1.f / l1, inv2 = lam / l2;
    #pragma unroll
    for (int i = 0; i < 8; i++)
        s1[tid + i * 256] = v1[i] * inv1 - v2[i] * inv2;
}

// ---------------------------------------------------------------------------
// O = W @ V per (b,h): 2048x128x2048; BN=128 covers all channels -> LN fused.
__global__ void __launch_bounds__(256)
ov_ln_kernel(const float* __restrict__ lng, const float* __restrict__ lnb) {
    int z = blockIdx.z;          // b*8 + h
    int b = z >> 3, h = z & 7;
    const float* A  = g_S + ((size_t)(b * 16 + 2 * h)) * Nq * Nq;  // combined W
    const float* Bm = g_v + (size_t)z * Nq * DV;

    extern __shared__ float sm[];
    float (*As)[132] = (float(*)[132])sm;                       // 16*132
    float (*Bs)[128] = (float(*)[128])(sm + 16 * 132);          // 16*128
    float (*Os)[132] = (float(*)[132])(sm + 16 * 132 + 16 * 128);  // 128*132

    int tid = threadIdx.x;
    int tx = tid & 15, ty = tid >> 4;
    int m0 = blockIdx.y * 128;
    int arow = tid >> 2, akv = (tid & 3) * 4;
    int brow = tid >> 5, bcol = (tid & 31) * 4;

    float acc[8][8];
    #pragma unroll
    for (int i = 0; i < 8; i++)
        #pragma unroll
        for (int j = 0; j < 8; j++) acc[i][j] = 0.f;

    for (int k0 = 0; k0 < 2048; k0 += 16) {
        #pragma unroll
        for (int hh = 0; hh < 2; hh++) {
            float4 av = *(const float4*)&A[(size_t)(m0 + arow + hh * 64) * 2048 + k0 + akv];
            As[akv + 0][arow + hh * 64] = av.x;
            As[akv + 1][arow + hh * 64] = av.y;
            As[akv + 2][arow + hh * 64] = av.z;
            As[akv + 3][arow + hh * 64] = av.w;
        }
        #pragma unroll
        for (int hh = 0; hh < 2; hh++) {
            float4 bv = *(const float4*)&Bm[(size_t)(k0 + brow + hh * 8) * 128 + bcol];
            *(float4*)&Bs[brow + hh * 8][bcol] = bv;
        }
        __syncthreads();
        #pragma unroll
        for (int kk = 0; kk < 16; kk++) {
            float a[8], bfr[8];
            *(float4*)&a[0] = *(float4*)&As[kk][ty * 8];
            *(float4*)&a[4] = *(float4*)&As[kk][ty * 8 + 4];
            *(float4*)&bfr[0] = *(float4*)&Bs[kk][tx * 8];
            *(float4*)&bfr[4] = *(float4*)&Bs[kk][tx * 8 + 4];
            #pragma unroll
            for (int i = 0; i < 8; i++)
                #pragma unroll
                for (int j = 0; j < 8; j++) acc[i][j] += a[i] * bfr[j];
        }
        __syncthreads();
    }

    #pragma unroll
    for (int i = 0; i < 8; i++)
        #pragma unroll
        for (int j = 0; j < 8; j++) Os[ty * 8 + i][tx * 8 + j] = acc[i][j];
    __syncthreads();

    int warp = tid >> 5, lane = tid & 31;
    for (int r0 = 0; r0 < 16; r0++) {
        int r = warp * 16 + r0;
        float s = 0.f, ss = 0.f;
        float vals[4];
        #pragma unroll
        for (int j = 0; j < 4; j++) {
            vals[j] = Os[r][lane + 32 * j];
            s  += vals[j];
            ss += vals[j] * vals[j];
        }
        #pragma unroll
        for (int o = 16; o; o >>= 1) {
            s  += __shfl_xor_sync(0xFFFFFFFFu, s, o);
            ss += __shfl_xor_sync(0xFFFFFFFFu, ss, o);
        }
        float mean = s * (1.f / 128.f);
        float var  = ss * (1.f / 128.f) - mean * mean;
        float rstd = rsqrtf(var + 1e-5f);
        int qrow = m0 + r;
        float* dst = g_o + ((size_t)(b * 2048 + qrow)) * 1024 + h * 128;
        #pragma unroll
        for (int j = 0; j < 4; j++) {
            int c = lane + 32 * j;
            dst[c] = (vals[j] - mean) * rstd * lng[c] + lnb[c];
        }
    }
}

// ---------------------------------------------------------------------------
extern "C" void kernel_launch(void* const* d_in, const int* in_sizes, int n_in,
                              void* d_out, int out_size) {
    const float* x   = (const float*)d_in[0];
    const float* Wq  = (const float*)d_in[1];
    const float* Wk  = (const float*)d_in[2];
    const float* Wv  = (const float*)d_in[3];
    const float* Wo  = (const float*)d_in[4];
    const float* lq1 = (const float*)d_in[5];
    const float* lk1 = (const float*)d_in[6];
    const float* lq2 = (const float*)d_in[7];
    const float* lk2 = (const float*)d_in[8];
    const float* lng = (const float*)d_in[9];
    const float* lnb = (const float*)d_in[10];
    float* out = (float*)d_out;

    lambda_kernel<<<1, 32>>>(lq1, lk1, lq2, lk2);

    dim3 gproj(1024 / 128, 4096 / 128);  // (8, 32)
    sgemm_nn_kernel<1><<<gproj, 256>>>(x, Wq, nullptr);
    sgemm_nn_kernel<2><<<gproj, 256>>>(x, Wk, nullptr);
    sgemm_nn_kernel<3><<<gproj, 256>>>(x, Wv, nullptr);

    scores_kernel<<<dim3(16, 16, 32), 256>>>();
    softmax_kernel<<<dim3(2048, 8, 2), 256>>>();

    const int smem_ov = (16 * 132 + 16 * 128 + 128 * 132) * 4;  // 84224 B
    cudaFuncSetAttribute(ov_ln_kernel, cudaFuncAttributeMaxDynamicSharedMemorySize, smem_ov);
    ov_ln_kernel<<<dim3(1, 16, 16), 256, smem_ov>>>(lng, lnb);

    sgemm_nn_kernel<0><<<gproj, 256>>>(nullptr, Wo, out);
}

// round 8
// speedup vs baseline: 2.9083x; 2.8980x over previous
#include <cuda_runtime.h>
#include <cuda_bf16.h>
#include <stdint.h>
#include <math.h>

// ---------------------------------------------------------------------------
// MultiheadDiffAttn (B=2, N=2048, E=1024, H=8, D=64, depth=12)
// bf16 hi/lo 3-term mma.sync (m16n8k16, fp32 accum) for all GEMMs.
// (tcgen05 unavailable: harness ptxas targets plain sm_103)
// ---------------------------------------------------------------------------

#define Bb 2
#define Nq 2048
#define Ee 1024
#define Hh 8
#define Mtok 4096

// ----------------- device scratch (allocation-free) ------------------------
__device__ __align__(16) __nv_bfloat16 g_xh[Mtok * Ee];
__device__ __align__(16) __nv_bfloat16 g_xl[Mtok * Ee];
__device__ __align__(16) __nv_bfloat16 g_wth[4][Ee * Ee];  // W^T [n][k]
__device__ __align__(16) __nv_bfloat16 g_wtl[4][Ee * Ee];
__device__ __align__(16) __nv_bfloat16 g_qh[Bb * 16 * Nq * 64];
__device__ __align__(16) __nv_bfloat16 g_ql[Bb * 16 * Nq * 64];
__device__ __align__(16) __nv_bfloat16 g_kh[Bb * 16 * Nq * 64];
__device__ __align__(16) __nv_bfloat16 g_kl[Bb * 16 * Nq * 64];
__device__ __align__(16) __nv_bfloat16 g_vnh[Bb * Hh * Nq * 128];  // [z][n][c]
__device__ __align__(16) __nv_bfloat16 g_vnl[Bb * Hh * Nq * 128];
__device__ __align__(16) __nv_bfloat16 g_vth[Bb * Hh * 128 * Nq];  // [z][c][n]
__device__ __align__(16) __nv_bfloat16 g_vtl[Bb * Hh * 128 * Nq];
__device__ float g_S[(size_t)Bb * 16 * Nq * Nq];                   // fp32 scores
__device__ __align__(16) __nv_bfloat16 g_Wh[(size_t)Bb * Hh * Nq * Nq];
__device__ __align__(16) __nv_bfloat16 g_Wl[(size_t)Bb * Hh * Nq * Nq];
__device__ __align__(16) __nv_bfloat16 g_oh[Mtok * Ee];
__device__ __align__(16) __nv_bfloat16 g_ol[Mtok * Ee];
__device__ float g_lambda;

// ----------------- helpers -------------------------------------------------
__device__ __forceinline__ uint32_t smem_to_u32(const void* p) {
    uint32_t a;
    asm("{ .reg .u64 t; cvta.to.shared.u64 t, %1; cvt.u32.u64 %0, t; }" : "=r"(a) : "l"(p));
    return a;
}
// SW128-style XOR swizzle on 128B rows
__device__ __forceinline__ uint32_t swz(uint32_t base, int r, int cb) {
    uint32_t off = (uint32_t)(r * 128 + cb);
    return base + (off ^ ((off >> 3) & 0x70));
}
__device__ __forceinline__ void ldsm_x4(uint32_t addr, uint32_t* r) {
    asm volatile("ldmatrix.sync.aligned.m8n8.x4.shared.b16 {%0,%1,%2,%3}, [%4];"
                 : "=r"(r[0]), "=r"(r[1]), "=r"(r[2]), "=r"(r[3]) : "r"(addr));
}
__device__ __forceinline__ void mma_bf16(float* c, const uint32_t* a, const uint32_t* b) {
    asm volatile(
        "mma.sync.aligned.m16n8k16.row.col.f32.bf16.bf16.f32 "
        "{%0,%1,%2,%3}, {%4,%5,%6,%7}, {%8,%9}, {%0,%1,%2,%3};"
        : "+f"(c[0]), "+f"(c[1]), "+f"(c[2]), "+f"(c[3])
        : "r"(a[0]), "r"(a[1]), "r"(a[2]), "r"(a[3]), "r"(b[0]), "r"(b[1]));
}
// A fragment (m16k16) from [m][k] tile, rows 128B swizzled
__device__ __forceinline__ void ldA(uint32_t tile, int mo, int kb, int lane, uint32_t* r) {
    int row = mo + (lane & 15);
    int cb = kb + ((lane >> 4) << 4);
    ldsm_x4(swz(tile, row, cb), r);
}
// B fragments (2x n8k16) from [n][k] tile
__device__ __forceinline__ void ldB(uint32_t tile, int no, int kb, int lane, uint32_t* r) {
    int row = no + ((lane >> 4) << 3) + (lane & 7);
    int cb = kb + (((lane >> 3) & 1) << 4);
    ldsm_x4(swz(tile, row, cb), r);
}
#define CP_COMMIT() asm volatile("cp.async.commit_group;" ::: "memory")
#define CP_WAIT(n)  asm volatile("cp.async.wait_group %0;" :: "n"(n) : "memory")

// async copy R rows x 64 bf16 into swizzled 128B-row smem
template <int R>
__device__ __forceinline__ void cp_tile64(uint32_t dst, const __nv_bfloat16* src,
                                          size_t ld, int tid) {
    #pragma unroll
    for (int i = tid; i < R * 8; i += 256) {
        int r = i >> 3, c8 = i & 7;
        uint32_t off = (uint32_t)((r << 7) | (c8 << 4));
        const void* g = src + (size_t)r * ld + c8 * 8;
        asm volatile("cp.async.cg.shared.global [%0], [%1], 16;"
                     :: "r"(dst + (off ^ ((off >> 3) & 0x70))), "l"(g) : "memory");
    }
}
// sync copy variant
template <int R>
__device__ __forceinline__ void ld_tile64(char* dst, const __nv_bfloat16* src,
                                          size_t ld, int tid) {
    #pragma unroll
    for (int i = tid; i < R * 8; i += 256) {
        int r = i >> 3, c8 = i & 7;
        uint4 v = *(const uint4*)(src + (size_t)r * ld + c8 * 8);
        uint32_t off = (uint32_t)((r << 7) | (c8 << 4));
        *(uint4*)(dst + (off ^ ((off >> 3) & 0x70))) = v;
    }
}
__device__ __forceinline__ void split2(float a, float b, uint32_t& hp, uint32_t& lp) {
    __nv_bfloat16 h0 = __float2bfloat16(a), h1 = __float2bfloat16(b);
    __nv_bfloat16 l0 = __float2bfloat16(a - __bfloat162float(h0));
    __nv_bfloat16 l1 = __float2bfloat16(b - __bfloat162float(h1));
    hp = (uint32_t)__bfloat16_as_ushort(h0) | ((uint32_t)__bfloat16_as_ushort(h1) << 16);
    lp = (uint32_t)__bfloat16_as_ushort(l0) | ((uint32_t)__bfloat16_as_ushort(l1) << 16);
}

// ---------------------------------------------------------------------------
__global__ void lambda_kernel(const float* lq1, const float* lk1,
                              const float* lq2, const float* lk2) {
    int t = threadIdx.x;
    float s1 = lq1[t] * lk1[t] + lq1[t + 32] * lk1[t + 32];
    float s2 = lq2[t] * lk2[t] + lq2[t + 32] * lk2[t + 32];
    #pragma unroll
    for (int o = 16; o; o >>= 1) {
        s1 += __shfl_xor_sync(0xFFFFFFFFu, s1, o);
        s2 += __shfl_xor_sync(0xFFFFFFFFu, s2, o);
    }
    if (t == 0) {
        float lam_init = 0.8f - 0.6f * expf(-0.3f * 12.0f);
        g_lambda = expf(s1) - expf(s2) + lam_init;
    }
}

__global__ void __launch_bounds__(256) convert_x(const float* __restrict__ x) {
    size_t i = ((size_t)blockIdx.x * 256 + threadIdx.x) * 4;
    float4 v = *(const float4*)(x + i);
    uint32_t h0, l0, h1, l1;
    split2(v.x, v.y, h0, l0);
    split2(v.z, v.w, h1, l1);
    *(uint2*)(g_xh + i) = make_uint2(h0, h1);
    *(uint2*)(g_xl + i) = make_uint2(l0, l1);
}

__global__ void transpose_w(const float* W0, const float* W1,
                            const float* W2, const float* W3) {
    __shared__ float t[32][33];
    int zi = blockIdx.z;
    const float* W = (zi == 0) ? W0 : (zi == 1) ? W1 : (zi == 2) ? W2 : W3;
    __nv_bfloat16* Th = g_wth[zi];
    __nv_bfloat16* Tl = g_wtl[zi];
    int n0 = blockIdx.x * 32, k0 = blockIdx.y * 32;
    int tx = threadIdx.x, ty = threadIdx.y;
    #pragma unroll
    for (int rr = 0; rr < 4; rr++)
        t[ty + 8 * rr][tx] = W[(size_t)(k0 + ty + 8 * rr) * 1024 + n0 + tx];
    __syncthreads();
    #pragma unroll
    for (int rr = 0; rr < 4; rr++) {
        float v = t[tx][ty + 8 * rr];
        __nv_bfloat16 hi = __float2bfloat16(v);
        __nv_bfloat16 lo = __float2bfloat16(v - __bfloat162float(hi));
        size_t o = (size_t)(n0 + ty + 8 * rr) * 1024 + k0 + tx;
        Th[o] = hi;
        Tl[o] = lo;
    }
}

__global__ void vtrans_kernel() {
    __shared__ __nv_bfloat16 th[32][33], tl[32][33];
    int z = blockIdx.z, n0 = blockIdx.x * 32, c0 = blockIdx.y * 32;
    int tx = threadIdx.x, ty = threadIdx.y;
    #pragma unroll
    for (int rr = 0; rr < 4; rr++) {
        size_t s = ((size_t)z * 2048 + n0 + ty + 8 * rr) * 128 + c0 + tx;
        th[ty + 8 * rr][tx] = g_vnh[s];
        tl[ty + 8 * rr][tx] = g_vnl[s];
    }
    __syncthreads();
    #pragma unroll
    for (int rr = 0; rr < 4; rr++) {
        size_t d = ((size_t)z * 128 + c0 + ty + 8 * rr) * 2048 + n0 + tx;
        g_vth[d] = th[tx][ty + 8 * rr];
        g_vtl[d] = tl[tx][ty + 8 * rr];
    }
}

// ---------------------------------------------------------------------------
// Big NN GEMM: [4096,1024] x W. CTA 128x128, 16 K-chunks of 64, cp.async db.
// mode: 0=q(*0.125) 1=k 2=v (bf16 hi/lo scatter)  3=out-proj (fp32)
__global__ void __launch_bounds__(256) gemm_big(int mode_sel, float* __restrict__ dout) {
    extern __shared__ __align__(1024) char sm[];
    const int tid = threadIdx.x, wid = tid >> 5, lane = tid & 31;
    const int gid = lane >> 2, tg = lane & 3;
    const int mode = (mode_sel < 0) ? (int)blockIdx.z : mode_sel;
    uint32_t t0 = (smem_to_u32(sm) + 1023) & ~1023u;

    const int m0 = blockIdx.y * 128, n0 = blockIdx.x * 128;
    const __nv_bfloat16* Agh = ((mode == 3) ? g_oh : g_xh) + (size_t)m0 * 1024;
    const __nv_bfloat16* Agl = ((mode == 3) ? g_ol : g_xl) + (size_t)m0 * 1024;
    const __nv_bfloat16* Bgh = g_wth[mode] + (size_t)n0 * 1024;
    const __nv_bfloat16* Bgl = g_wtl[mode] + (size_t)n0 * 1024;

    const int mw = (wid >> 1) * 32, nw = (wid & 1) * 64;
    float acc[2][8][4];
    #pragma unroll
    for (int i = 0; i < 2; i++)
        #pragma unroll
        for (int j = 0; j < 8; j++)
            #pragma unroll
            for (int r = 0; r < 4; r++) acc[i][j][r] = 0.f;

    auto issue = [&](int st, int c) {
        uint32_t s = t0 + st * 65536;
        cp_tile64<128>(s,         Agh + c * 64, 1024, tid);
        cp_tile64<128>(s + 16384, Agl + c * 64, 1024, tid);
        cp_tile64<128>(s + 32768, Bgh + c * 64, 1024, tid);
        cp_tile64<128>(s + 49152, Bgl + c * 64, 1024, tid);
        CP_COMMIT();
    };
    issue(0, 0);
    #pragma unroll 1
    for (int c = 0; c < 16; c++) {
        if (c < 15) { issue((c + 1) & 1, c + 1); CP_WAIT(1); }
        else CP_WAIT(0);
        __syncthreads();
        uint32_t s = t0 + (c & 1) * 65536;
        uint32_t Ah = s, Al = s + 16384, Bh = s + 32768, Bl = s + 49152;
        #pragma unroll
        for (int ks = 0; ks < 4; ks++) {
            int kb = ks * 32;
            uint32_t ah[2][4], al[2][4], bh[4][4], bl[4][4];
            #pragma unroll
            for (int am = 0; am < 2; am++) {
                ldA(Ah, mw + am * 16, kb, lane, ah[am]);
                ldA(Al, mw + am * 16, kb, lane, al[am]);
            }
            #pragma unroll
            for (int bn = 0; bn < 4; bn++) {
                ldB(Bh, nw + bn * 16, kb, lane, bh[bn]);
                ldB(Bl, nw + bn * 16, kb, lane, bl[bn]);
            }
            #pragma unroll
            for (int am = 0; am < 2; am++)
                #pragma unroll
                for (int an = 0; an < 8; an++) {
                    const uint32_t* bbh = &bh[an >> 1][(an & 1) * 2];
                    const uint32_t* bbl = &bl[an >> 1][(an & 1) * 2];
                    mma_bf16(acc[am][an], ah[am], bbh);
                    mma_bf16(acc[am][an], ah[am], bbl);
                    mma_bf16(acc[am][an], al[am], bbh);
                }
        }
        __syncthreads();
    }

    #pragma unroll
    for (int am = 0; am < 2; am++) {
        int r0 = m0 + mw + am * 16 + gid;
        #pragma unroll
        for (int an = 0; an < 8; an++) {
            int gc = n0 + nw + an * 8 + tg * 2;
            float* a = acc[am][an];
            if (mode == 3) {
                *(float2*)(dout + (size_t)r0 * 1024 + gc) = make_float2(a[0], a[1]);
                *(float2*)(dout + (size_t)(r0 + 8) * 1024 + gc) = make_float2(a[2], a[3]);
            } else {
                float sc = (mode == 0) ? 0.125f : 1.f;
                #pragma unroll
                for (int rp = 0; rp < 2; rp++) {
                    int gm = r0 + rp * 8, bb = gm >> 11, nn = gm & 2047;
                    uint32_t hp, lp;
                    split2(a[rp * 2] * sc, a[rp * 2 + 1] * sc, hp, lp);
                    size_t di;
                    __nv_bfloat16 *Dh, *Dl;
                    if (mode == 2) {
                        int h = gc >> 7, ch = gc & 127;
                        di = ((size_t)((bb * 8 + h) * 2048 + nn)) * 128 + ch;
                        Dh = g_vnh; Dl = g_vnl;
                    } else {
                        int hh = gc >> 6, d = gc & 63;
                        di = ((size_t)((bb * 16 + hh) * 2048 + nn)) * 64 + d;
                        Dh = (mode == 0) ? g_qh : g_kh;
                        Dl = (mode == 0) ? g_ql : g_kl;
                    }
                    *(uint32_t*)(Dh + di) = hp;
                    *(uint32_t*)(Dl + di) = lp;
                }
            }
        }
    }
}

// ---------------------------------------------------------------------------
// Scores: S[z] = Q[z] @ K[z]^T, CTA 128x128, K=64 (one chunk), fp32 out.
__global__ void __launch_bounds__(256) gemm_scores() {
    extern __shared__ __align__(1024) char sm[];
    const int tid = threadIdx.x, wid = tid >> 5, lane = tid & 31;
    const int gid = lane >> 2, tg = lane & 3;
    uint32_t t0 = (smem_to_u32(sm) + 1023) & ~1023u;
    char* t0p = sm + (t0 - smem_to_u32(sm));

    int z = blockIdx.z, m0 = blockIdx.y * 128, n0 = blockIdx.x * 128;
    ld_tile64<128>(t0p,         g_qh + ((size_t)z * 2048 + m0) * 64, 64, tid);
    ld_tile64<128>(t0p + 16384, g_ql + ((size_t)z * 2048 + m0) * 64, 64, tid);
    ld_tile64<128>(t0p + 32768, g_kh + ((size_t)z * 2048 + n0) * 64, 64, tid);
    ld_tile64<128>(t0p + 49152, g_kl + ((size_t)z * 2048 + n0) * 64, 64, tid);
    __syncthreads();

    const int mw = (wid >> 1) * 32, nw = (wid & 1) * 64;
    float acc[2][8][4];
    #pragma unroll
    for (int i = 0; i < 2; i++)
        #pragma unroll
        for (int j = 0; j < 8; j++)
            #pragma unroll
            for (int r = 0; r < 4; r++) acc[i][j][r] = 0.f;

    uint32_t Ah = t0, Al = t0 + 16384, Bh = t0 + 32768, Bl = t0 + 49152;
    #pragma unroll
    for (int ks = 0; ks < 4; ks++) {
        int kb = ks * 32;
        uint32_t ah[2][4], al[2][4], bh[4][4], bl[4][4];
        #pragma unroll
        for (int am = 0; am < 2; am++) {
            ldA(Ah, mw + am * 16, kb, lane, ah[am]);
            ldA(Al, mw + am * 16, kb, lane, al[am]);
        }
        #pragma unroll
        for (int bn = 0; bn < 4; bn++) {
            ldB(Bh, nw + bn * 16, kb, lane, bh[bn]);
            ldB(Bl, nw + bn * 16, kb, lane, bl[bn]);
        }
        #pragma unroll
        for (int am = 0; am < 2; am++)
            #pragma unroll
            for (int an = 0; an < 8; an++) {
                const uint32_t* bbh = &bh[an >> 1][(an & 1) * 2];
                const uint32_t* bbl = &bl[an >> 1][(an & 1) * 2];
                mma_bf16(acc[am][an], ah[am], bbh);
                mma_bf16(acc[am][an], ah[am], bbl);
                mma_bf16(acc[am][an], al[am], bbh);
            }
    }

    float* C = g_S + ((size_t)z * 2048 + m0) * 2048 + n0;
    #pragma unroll
    for (int am = 0; am < 2; am++) {
        int r0 = mw + am * 16 + gid;
        #pragma unroll
        for (int an = 0; an < 8; an++) {
            int gc = nw + an * 8 + tg * 2;
            float* a = acc[am][an];
            *(float2*)(C + (size_t)r0 * 2048 + gc) = make_float2(a[0], a[1]);
            *(float2*)(C + (size_t)(r0 + 8) * 2048 + gc) = make_float2(a[2], a[3]);
        }
    }
}

// ---------------------------------------------------------------------------
// Softmax pair + lambda combine -> hi/lo bf16 combined weights
__global__ void __launch_bounds__(256) softmax_kernel() {
    int q = blockIdx.x, h = blockIdx.y, b = blockIdx.z;
    float lam = g_lambda;
    const float* s1 = g_S + ((size_t)(b * 16 + 2 * h)) * Nq * Nq + (size_t)q * Nq;
    const float* s2 = s1 + (size_t)Nq * Nq;
    __nv_bfloat16* wh = g_Wh + ((size_t)(b * 8 + h) * 2048 + q) * 2048;
    __nv_bfloat16* wl = g_Wl + ((size_t)(b * 8 + h) * 2048 + q) * 2048;

    int tid = threadIdx.x;
    float v1[8], v2[8], m1 = -1e30f, m2 = -1e30f;
    #pragma unroll
    for (int i = 0; i < 8; i++) {
        v1[i] = s1[tid + i * 256];
        v2[i] = s2[tid + i * 256];
        m1 = fmaxf(m1, v1[i]);
        m2 = fmaxf(m2, v2[i]);
    }
    __shared__ float red1[8], red2[8], su1[8], su2[8];
    #pragma unroll
    for (int o = 16; o; o >>= 1) {
        m1 = fmaxf(m1, __shfl_xor_sync(0xFFFFFFFFu, m1, o));
        m2 = fmaxf(m2, __shfl_xor_sync(0xFFFFFFFFu, m2, o));
    }
    int warp = tid >> 5, lane = tid & 31;
    if (lane == 0) { red1[warp] = m1; red2[warp] = m2; }
    __syncthreads();
    m1 = red1[0]; m2 = red2[0];
    #pragma unroll
    for (int w = 1; w < 8; w++) { m1 = fmaxf(m1, red1[w]); m2 = fmaxf(m2, red2[w]); }
    float l1 = 0.f, l2 = 0.f;
    #pragma unroll
    for (int i = 0; i < 8; i++) {
        v1[i] = __expf(v1[i] - m1); l1 += v1[i];
        v2[i] = __expf(v2[i] - m2); l2 += v2[i];
    }
    #pragma unroll
    for (int o = 16; o; o >>= 1) {
        l1 += __shfl_xor_sync(0xFFFFFFFFu, l1, o);
        l2 += __shfl_xor_sync(0xFFFFFFFFu, l2, o);
    }
    if (lane == 0) { su1[warp] = l1; su2[warp] = l2; }
    __syncthreads();
    l1 = su1[0]; l2 = su2[0];
    #pragma unroll
    for (int w = 1; w < 8; w++) { l1 += su1[w]; l2 += su2[w]; }
    float inv1 = 1.f / l1, inv2 = lam / l2;
    #pragma unroll
    for (int i = 0; i < 8; i++) {
        float w = v1[i] * inv1 - v2[i] * inv2;
        __nv_bfloat16 hh = __float2bfloat16(w);
        __nv_bfloat16 ll = __float2bfloat16(w - __bfloat162float(hh));
        wh[tid + i * 256] = hh;
        wl[tid + i * 256] = ll;
    }
}

// ---------------------------------------------------------------------------
// PV: O[2048,128] = Wc[2048,2048] @ V^T. CTA 128x128, warp=16m x 128n, LN fused.
__global__ void __launch_bounds__(256) gemm_pv(const float* __restrict__ lng,
                                               const float* __restrict__ lnb) {
    extern __shared__ __align__(1024) char sm[];
    const int tid = threadIdx.x, wid = tid >> 5, lane = tid & 31;
    const int gid = lane >> 2, tg = lane & 3;
    uint32_t t0 = (smem_to_u32(sm) + 1023) & ~1023u;

    int z = blockIdx.z, b = z >> 3, h = z & 7, m0 = blockIdx.y * 128;
    const __nv_bfloat16* Agh = g_Wh + ((size_t)z * 2048 + m0) * 2048;
    const __nv_bfloat16* Agl = g_Wl + ((size_t)z * 2048 + m0) * 2048;
    const __nv_bfloat16* Bgh = g_vth + (size_t)z * 128 * 2048;
    const __nv_bfloat16* Bgl = g_vtl + (size_t)z * 128 * 2048;

    const int mw = wid * 16;
    float acc[16][4];
    #pragma unroll
    for (int j = 0; j < 16; j++)
        #pragma unroll
        for (int r = 0; r < 4; r++) acc[j][r] = 0.f;

    auto issue = [&](int st, int c) {
        uint32_t s = t0 + st * 65536;
        cp_tile64<128>(s,         Agh + c * 64, 2048, tid);
        cp_tile64<128>(s + 16384, Agl + c * 64, 2048, tid);
        cp_tile64<128>(s + 32768, Bgh + c * 64, 2048, tid);
        cp_tile64<128>(s + 49152, Bgl + c * 64, 2048, tid);
        CP_COMMIT();
    };
    issue(0, 0);
    #pragma unroll 1
    for (int c = 0; c < 32; c++) {
        if (c < 31) { issue((c + 1) & 1, c + 1); CP_WAIT(1); }
        else CP_WAIT(0);
        __syncthreads();
        uint32_t s = t0 + (c & 1) * 65536;
        uint32_t Ah = s, Al = s + 16384, Bh = s + 32768, Bl = s + 49152;
        #pragma unroll
        for (int ks = 0; ks < 4; ks++) {
            int kb = ks * 32;
            uint32_t ah[4], al[4], bh[8][4], bl[8][4];
            ldA(Ah, mw, kb, lane, ah);
            ldA(Al, mw, kb, lane, al);
            #pragma unroll
            for (int bn = 0; bn < 8; bn++) {
                ldB(Bh, bn * 16, kb, lane, bh[bn]);
                ldB(Bl, bn * 16, kb, lane, bl[bn]);
            }
            #pragma unroll
            for (int an = 0; an < 16; an++) {
                const uint32_t* bbh = &bh[an >> 1][(an & 1) * 2];
                const uint32_t* bbl = &bl[an >> 1][(an & 1) * 2];
                mma_bf16(acc[an], ah, bbh);
                mma_bf16(acc[an], ah, bbl);
                mma_bf16(acc[an], al, bbh);
            }
        }
        __syncthreads();
    }

    // per-row LayerNorm(128): quad-reduce (4 threads share a row)
    float s0 = 0.f, q0 = 0.f, s1 = 0.f, q1 = 0.f;
    #pragma unroll
    for (int an = 0; an < 16; an++) {
        s0 += acc[an][0] + acc[an][1];
        q0 += acc[an][0] * acc[an][0] + acc[an][1] * acc[an][1];
        s1 += acc[an][2] + acc[an][3];
        q1 += acc[an][2] * acc[an][2] + acc[an][3] * acc[an][3];
    }
    #pragma unroll
    for (int o = 1; o <= 2; o <<= 1) {
        s0 += __shfl_xor_sync(0xFFFFFFFFu, s0, o);
        q0 += __shfl_xor_sync(0xFFFFFFFFu, q0, o);
        s1 += __shfl_xor_sync(0xFFFFFFFFu, s1, o);
        q1 += __shfl_xor_sync(0xFFFFFFFFu, q1, o);
    }
    float mu0 = s0 * (1.f / 128.f), mu1 = s1 * (1.f / 128.f);
    float r0s = rsqrtf(q0 * (1.f / 128.f) - mu0 * mu0 + 1e-5f);
    float r1s = rsqrtf(q1 * (1.f / 128.f) - mu1 * mu1 + 1e-5f);
    int rowA = m0 + mw + gid;
    size_t baseA = ((size_t)(b * 2048 + rowA)) * 1024 + h * 128;
    size_t baseB = ((size_t)(b * 2048 + rowA + 8)) * 1024 + h * 128;
    #pragma unroll
    for (int an = 0; an < 16; an++) {
        int c = an * 8 + tg * 2;
        float ga = lng[c], gb = lng[c + 1], ba = lnb[c], bb2 = lnb[c + 1];
        float w0 = (acc[an][0] - mu0) * r0s * ga + ba;
        float w1 = (acc[an][1] - mu0) * r0s * gb + bb2;
        uint32_t hp, lp;
        split2(w0, w1, hp, lp);
        *(uint32_t*)(g_oh + baseA + c) = hp;
        *(uint32_t*)(g_ol + baseA + c) = lp;
        float w2 = (acc[an][2] - mu1) * r1s * ga + ba;
        float w3 = (acc[an][3] - mu1) * r1s * gb + bb2;
        split2(w2, w3, hp, lp);
        *(uint32_t*)(g_oh + baseB + c) = hp;
        *(uint32_t*)(g_ol + baseB + c) = lp;
    }
}

// ---------------------------------------------------------------------------
extern "C" void kernel_launch(void* const* d_in, const int* in_sizes, int n_in,
                              void* d_out, int out_size) {
    const float* x   = (const float*)d_in[0];
    const float* Wq  = (const float*)d_in[1];
    const float* Wk  = (const float*)d_in[2];
    const float* Wv  = (const float*)d_in[3];
    const float* Wo  = (const float*)d_in[4];
    const float* lq1 = (const float*)d_in[5];
    const float* lk1 = (const float*)d_in[6];
    const float* lq2 = (const float*)d_in[7];
    const float* lk2 = (const float*)d_in[8];
    const float* lng = (const float*)d_in[9];
    const float* lnb = (const float*)d_in[10];
    float* out = (float*)d_out;

    const int SM_DB = 2 * 65536 + 1024;  // 132096
    const int SM_SC = 65536 + 1024;      // 66560
    cudaFuncSetAttribute(gemm_big, cudaFuncAttributeMaxDynamicSharedMemorySize, SM_DB);
    cudaFuncSetAttribute(gemm_scores, cudaFuncAttributeMaxDynamicSharedMemorySize, SM_SC);
    cudaFuncSetAttribute(gemm_pv, cudaFuncAttributeMaxDynamicSharedMemorySize, SM_DB);

    lambda_kernel<<<1, 32>>>(lq1, lk1, lq2, lk2);
    convert_x<<<4096, 256>>>(x);
    transpose_w<<<dim3(32, 32, 4), dim3(32, 8)>>>(Wq, Wk, Wv, Wo);

    gemm_big<<<dim3(8, 32, 3), 256, SM_DB>>>(-1, nullptr);   // q,k,v projections
    vtrans_kernel<<<dim3(64, 4, 16), dim3(32, 8)>>>();
    gemm_scores<<<dim3(16, 16, 32), 256, SM_SC>>>();
    softmax_kernel<<<dim3(2048, 8, 2), 256>>>();
    gemm_pv<<<dim3(1, 16, 16), 256, SM_DB>>>(lng, lnb);
    gemm_big<<<dim3(8, 32, 1), 256, SM_DB>>>(3, out);        // output projection
}

// round 9
// speedup vs baseline: 2.9967x; 1.0304x over previous
#include <cuda_runtime.h>
#include <cuda_bf16.h>
#include <stdint.h>
#include <math.h>

// ---------------------------------------------------------------------------
// MultiheadDiffAttn (B=2, N=2048, E=1024, H=8, D=64, depth=12)
// bf16 hi/lo 3-term mma.sync (m16n8k16, fp32 accum) for all GEMMs.
// R9: 2-CTA occupancy (K-chunk 32, 3-stage cp.async, launch_bounds(256,2)),
//     PV m-tile 64, scores cp.async, softmax vectorized.
// ---------------------------------------------------------------------------

#define Bb 2
#define Nq 2048
#define Ee 1024
#define Hh 8
#define Mtok 4096

__device__ __align__(16) __nv_bfloat16 g_xh[Mtok * Ee];
__device__ __align__(16) __nv_bfloat16 g_xl[Mtok * Ee];
__device__ __align__(16) __nv_bfloat16 g_wth[4][Ee * Ee];
__device__ __align__(16) __nv_bfloat16 g_wtl[4][Ee * Ee];
__device__ __align__(16) __nv_bfloat16 g_qh[Bb * 16 * Nq * 64];
__device__ __align__(16) __nv_bfloat16 g_ql[Bb * 16 * Nq * 64];
__device__ __align__(16) __nv_bfloat16 g_kh[Bb * 16 * Nq * 64];
__device__ __align__(16) __nv_bfloat16 g_kl[Bb * 16 * Nq * 64];
__device__ __align__(16) __nv_bfloat16 g_vnh[Bb * Hh * Nq * 128];
__device__ __align__(16) __nv_bfloat16 g_vnl[Bb * Hh * Nq * 128];
__device__ __align__(16) __nv_bfloat16 g_vth[Bb * Hh * 128 * Nq];
__device__ __align__(16) __nv_bfloat16 g_vtl[Bb * Hh * 128 * Nq];
__device__ float g_S[(size_t)Bb * 16 * Nq * Nq];
__device__ __align__(16) __nv_bfloat16 g_Wh[(size_t)Bb * Hh * Nq * Nq];
__device__ __align__(16) __nv_bfloat16 g_Wl[(size_t)Bb * Hh * Nq * Nq];
__device__ __align__(16) __nv_bfloat16 g_oh[Mtok * Ee];
__device__ __align__(16) __nv_bfloat16 g_ol[Mtok * Ee];
__device__ float g_lambda;

__device__ __forceinline__ uint32_t smem_to_u32(const void* p) {
    uint32_t a;
    asm("{ .reg .u64 t; cvta.to.shared.u64 t, %1; cvt.u32.u64 %0, t; }" : "=r"(a) : "l"(p));
    return a;
}
__device__ __forceinline__ void ldsm_x4(uint32_t addr, uint32_t* r) {
    asm volatile("ldmatrix.sync.aligned.m8n8.x4.shared.b16 {%0,%1,%2,%3}, [%4];"
                 : "=r"(r[0]), "=r"(r[1]), "=r"(r[2]), "=r"(r[3]) : "r"(addr));
}
__device__ __forceinline__ void mma_bf16(float* c, const uint32_t* a, const uint32_t* b) {
    asm volatile(
        "mma.sync.aligned.m16n8k16.row.col.f32.bf16.bf16.f32 "
        "{%0,%1,%2,%3}, {%4,%5,%6,%7}, {%8,%9}, {%0,%1,%2,%3};"
        : "+f"(c[0]), "+f"(c[1]), "+f"(c[2]), "+f"(c[3])
        : "r"(a[0]), "r"(a[1]), "r"(a[2]), "r"(a[3]), "r"(b[0]), "r"(b[1]));
}
template <int RB>
__device__ __forceinline__ void ldA(uint32_t tile, int mo, int kb, int lane, uint32_t* r) {
    int row = mo + (lane & 15);
    int cb = kb + ((lane >> 4) << 4);
    uint32_t off = (uint32_t)(row * RB + cb);
    ldsm_x4(tile + (off ^ ((off >> 3) & 0x70)), r);
}
template <int RB>
__device__ __forceinline__ void ldB(uint32_t tile, int no, int kb, int lane, uint32_t* r) {
    int row = no + ((lane >> 4) << 3) + (lane & 7);
    int cb = kb + (((lane >> 3) & 1) << 4);
    uint32_t off = (uint32_t)(row * RB + cb);
    ldsm_x4(tile + (off ^ ((off >> 3) & 0x70)), r);
}
#define CP_COMMIT() asm volatile("cp.async.commit_group;" ::: "memory")
#define CP_WAIT(n)  asm volatile("cp.async.wait_group %0;" :: "n"(n) : "memory")

template <int R>
__device__ __forceinline__ void cp_tile32(uint32_t dst, const __nv_bfloat16* src,
                                          size_t ld, int tid) {
    #pragma unroll
    for (int i = tid; i < R * 4; i += 256) {
        int r = i >> 2, c8 = i & 3;
        uint32_t off = (uint32_t)((r << 6) | (c8 << 4));
        const void* g = src + (size_t)r * ld + c8 * 8;
        asm volatile("cp.async.cg.shared.global [%0], [%1], 16;"
                     :: "r"(dst + (off ^ ((off >> 3) & 0x70))), "l"(g) : "memory");
    }
}
template <int R>
__device__ __forceinline__ void cp_tile64(uint32_t dst, const __nv_bfloat16* src,
                                          size_t ld, int tid) {
    #pragma unroll
    for (int i = tid; i < R * 8; i += 256) {
        int r = i >> 3, c8 = i & 7;
        uint32_t off = (uint32_t)((r << 7) | (c8 << 4));
        const void* g = src + (size_t)r * ld + c8 * 8;
        asm volatile("cp.async.cg.shared.global [%0], [%1], 16;"
                     :: "r"(dst + (off ^ ((off >> 3) & 0x70))), "l"(g) : "memory");
    }
}
__device__ __forceinline__ void split2(float a, float b, uint32_t& hp, uint32_t& lp) {
    __nv_bfloat16 h0 = __float2bfloat16(a), h1 = __float2bfloat16(b);
    __nv_bfloat16 l0 = __float2bfloat16(a - __bfloat162float(h0));
    __nv_bfloat16 l1 = __float2bfloat16(b - __bfloat162float(h1));
    hp = (uint32_t)__bfloat16_as_ushort(h0) | ((uint32_t)__bfloat16_as_ushort(h1) << 16);
    lp = (uint32_t)__bfloat16_as_ushort(l0) | ((uint32_t)__bfloat16_as_ushort(l1) << 16);
}

// ---------------------------------------------------------------------------
__global__ void lambda_kernel(const float* lq1, const float* lk1,
                              const float* lq2, const float* lk2) {
    int t = threadIdx.x;
    float s1 = lq1[t] * lk1[t] + lq1[t + 32] * lk1[t + 32];
    float s2 = lq2[t] * lk2[t] + lq2[t + 32] * lk2[t + 32];
    #pragma unroll
    for (int o = 16; o; o >>= 1) {
        s1 += __shfl_xor_sync(0xFFFFFFFFu, s1, o);
        s2 += __shfl_xor_sync(0xFFFFFFFFu, s2, o);
    }
    if (t == 0) {
        float lam_init = 0.8f - 0.6f * expf(-0.3f * 12.0f);
        g_lambda = expf(s1) - expf(s2) + lam_init;
    }
}

__global__ void __launch_bounds__(256) convert_x(const float* __restrict__ x) {
    size_t i = ((size_t)blockIdx.x * 256 + threadIdx.x) * 4;
    float4 v = *(const float4*)(x + i);
    uint32_t h0, l0, h1, l1;
    split2(v.x, v.y, h0, l0);
    split2(v.z, v.w, h1, l1);
    *(uint2*)(g_xh + i) = make_uint2(h0, h1);
    *(uint2*)(g_xl + i) = make_uint2(l0, l1);
}

__global__ void transpose_w(const float* W0, const float* W1,
                            const float* W2, const float* W3) {
    __shared__ float t[32][33];
    int zi = blockIdx.z;
    const float* W = (zi == 0) ? W0 : (zi == 1) ? W1 : (zi == 2) ? W2 : W3;
    __nv_bfloat16* Th = g_wth[zi];
    __nv_bfloat16* Tl = g_wtl[zi];
    int n0 = blockIdx.x * 32, k0 = blockIdx.y * 32;
    int tx = threadIdx.x, ty = threadIdx.y;
    #pragma unroll
    for (int rr = 0; rr < 4; rr++)
        t[ty + 8 * rr][tx] = W[(size_t)(k0 + ty + 8 * rr) * 1024 + n0 + tx];
    __syncthreads();
    #pragma unroll
    for (int rr = 0; rr < 4; rr++) {
        float v = t[tx][ty + 8 * rr];
        __nv_bfloat16 hi = __float2bfloat16(v);
        __nv_bfloat16 lo = __float2bfloat16(v - __bfloat162float(hi));
        size_t o = (size_t)(n0 + ty + 8 * rr) * 1024 + k0 + tx;
        Th[o] = hi;
        Tl[o] = lo;
    }
}

__global__ void vtrans_kernel() {
    __shared__ __nv_bfloat16 th[32][33], tl[32][33];
    int z = blockIdx.z, n0 = blockIdx.x * 32, c0 = blockIdx.y * 32;
    int tx = threadIdx.x, ty = threadIdx.y;
    #pragma unroll
    for (int rr = 0; rr < 4; rr++) {
        size_t s = ((size_t)z * 2048 + n0 + ty + 8 * rr) * 128 + c0 + tx;
        th[ty + 8 * rr][tx] = g_vnh[s];
        tl[ty + 8 * rr][tx] = g_vnl[s];
    }
    __syncthreads();
    #pragma unroll
    for (int rr = 0; rr < 4; rr++) {
        size_t d = ((size_t)z * 128 + c0 + ty + 8 * rr) * 2048 + n0 + tx;
        g_vth[d] = th[tx][ty + 8 * rr];
        g_vtl[d] = tl[tx][ty + 8 * rr];
    }
}

// ---------------------------------------------------------------------------
#define BSTG 32768
__global__ void __launch_bounds__(256, 2) gemm_big(int mode_sel, float* __restrict__ dout) {
    extern __shared__ __align__(1024) char sm[];
    const int tid = threadIdx.x, wid = tid >> 5, lane = tid & 31;
    const int gid = lane >> 2, tg = lane & 3;
    const int mode = (mode_sel < 0) ? (int)blockIdx.z : mode_sel;
    uint32_t t0 = (smem_to_u32(sm) + 1023) & ~1023u;

    const int m0 = blockIdx.y * 128, n0 = blockIdx.x * 128;
    const __nv_bfloat16* Agh = ((mode == 3) ? g_oh : g_xh) + (size_t)m0 * 1024;
    const __nv_bfloat16* Agl = ((mode == 3) ? g_ol : g_xl) + (size_t)m0 * 1024;
    const __nv_bfloat16* Bgh = g_wth[mode] + (size_t)n0 * 1024;
    const __nv_bfloat16* Bgl = g_wtl[mode] + (size_t)n0 * 1024;

    const int mw = (wid >> 1) * 32, nw = (wid & 1) * 64;
    float acc[2][8][4];
    #pragma unroll
    for (int i = 0; i < 2; i++)
        #pragma unroll
        for (int j = 0; j < 8; j++)
            #pragma unroll
            for (int r = 0; r < 4; r++) acc[i][j][r] = 0.f;

    auto issue = [&](int st, int c) {
        uint32_t s = t0 + st * BSTG;
        cp_tile32<128>(s,         Agh + c * 32, 1024, tid);
        cp_tile32<128>(s + 8192,  Agl + c * 32, 1024, tid);
        cp_tile32<128>(s + 16384, Bgh + c * 32, 1024, tid);
        cp_tile32<128>(s + 24576, Bgl + c * 32, 1024, tid);
        CP_COMMIT();
    };
    const int NC = 32;
    issue(0, 0);
    issue(1, 1);
    #pragma unroll 1
    for (int c = 0; c < NC; c++) {
        if (c + 2 < NC) { issue((c + 2) % 3, c + 2); CP_WAIT(2); }
        else if (c == NC - 2) CP_WAIT(1);
        else CP_WAIT(0);
        __syncthreads();
        uint32_t s = t0 + (c % 3) * BSTG;
        uint32_t Ah = s, Al = s + 8192, Bh = s + 16384, Bl = s + 24576;
        #pragma unroll
        for (int ks = 0; ks < 2; ks++) {
            int kb = ks * 32;
            uint32_t ah[2][4], al[2][4];
            #pragma unroll
            for (int am = 0; am < 2; am++) {
                ldA<64>(Ah, mw + am * 16, kb, lane, ah[am]);
                ldA<64>(Al, mw + am * 16, kb, lane, al[am]);
            }
            #pragma unroll
            for (int bn = 0; bn < 4; bn++) {
                uint32_t bh[4], bl[4];
                ldB<64>(Bh, nw + bn * 16, kb, lane, bh);
                ldB<64>(Bl, nw + bn * 16, kb, lane, bl);
                #pragma unroll
                for (int am = 0; am < 2; am++)
                    #pragma unroll
                    for (int sub = 0; sub < 2; sub++) {
                        float* a = acc[am][bn * 2 + sub];
                        mma_bf16(a, ah[am], &bh[sub * 2]);
                        mma_bf16(a, ah[am], &bl[sub * 2]);
                        mma_bf16(a, al[am], &bh[sub * 2]);
                    }
            }
        }
        __syncthreads();
    }

    #pragma unroll
    for (int am = 0; am < 2; am++) {
        int r0 = m0 + mw + am * 16 + gid;
        #pragma unroll
        for (int an = 0; an < 8; an++) {
            int gc = n0 + nw + an * 8 + tg * 2;
            float* a = acc[am][an];
            if (mode == 3) {
                *(float2*)(dout + (size_t)r0 * 1024 + gc) = make_float2(a[0], a[1]);
                *(float2*)(dout + (size_t)(r0 + 8) * 1024 + gc) = make_float2(a[2], a[3]);
            } else {
                float sc = (mode == 0) ? 0.125f : 1.f;
                #pragma unroll
                for (int rp = 0; rp < 2; rp++) {
                    int gm = r0 + rp * 8, bb = gm >> 11, nn = gm & 2047;
                    uint32_t hp, lp;
                    split2(a[rp * 2] * sc, a[rp * 2 + 1] * sc, hp, lp);
                    size_t di;
                    __nv_bfloat16 *Dh, *Dl;
                    if (mode == 2) {
                        int h = gc >> 7, ch = gc & 127;
                        di = ((size_t)((bb * 8 + h) * 2048 + nn)) * 128 + ch;
                        Dh = g_vnh; Dl = g_vnl;
                    } else {
                        int hh = gc >> 6, d = gc & 63;
                        di = ((size_t)((bb * 16 + hh) * 2048 + nn)) * 64 + d;
                        Dh = (mode == 0) ? g_qh : g_kh;
                        Dl = (mode == 0) ? g_ql : g_kl;
                    }
                    *(uint32_t*)(Dh + di) = hp;
                    *(uint32_t*)(Dl + di) = lp;
                }
            }
        }
    }
}

// ---------------------------------------------------------------------------
__global__ void __launch_bounds__(256, 2) gemm_scores() {
    extern __shared__ __align__(1024) char sm[];
    const int tid = threadIdx.x, wid = tid >> 5, lane = tid & 31;
    const int gid = lane >> 2, tg = lane & 3;
    uint32_t t0 = (smem_to_u32(sm) + 1023) & ~1023u;

    int z = blockIdx.z, m0 = blockIdx.y * 128, n0 = blockIdx.x * 128;
    cp_tile64<128>(t0,         g_qh + ((size_t)z * 2048 + m0) * 64, 64, tid);
    cp_tile64<128>(t0 + 16384, g_ql + ((size_t)z * 2048 + m0) * 64, 64, tid);
    cp_tile64<128>(t0 + 32768, g_kh + ((size_t)z * 2048 + n0) * 64, 64, tid);
    cp_tile64<128>(t0 + 49152, g_kl + ((size_t)z * 2048 + n0) * 64, 64, tid);
    CP_COMMIT();
    CP_WAIT(0);
    __syncthreads();

    const int mw = (wid >> 1) * 32, nw = (wid & 1) * 64;
    float acc[2][8][4];
    #pragma unroll
    for (int i = 0; i < 2; i++)
        #pragma unroll
        for (int j = 0; j < 8; j++)
            #pragma unroll
            for (int r = 0; r < 4; r++) acc[i][j][r] = 0.f;

    uint32_t Ah = t0, Al = t0 + 16384, Bh = t0 + 32768, Bl = t0 + 49152;
    #pragma unroll
    for (int ks = 0; ks < 4; ks++) {
        int kb = ks * 32;
        uint32_t ah[2][4], al[2][4];
        #pragma unroll
        for (int am = 0; am < 2; am++) {
            ldA<128>(Ah, mw + am * 16, kb, lane, ah[am]);
            ldA<128>(Al, mw + am * 16, kb, lane, al[am]);
        }
        #pragma unroll
        for (int bn = 0; bn < 4; bn++) {
            uint32_t bh[4], bl[4];
            ldB<128>(Bh, nw + bn * 16, kb, lane, bh);
            ldB<128>(Bl, nw + bn * 16, kb, lane, bl);
            #pragma unroll
            for (int am = 0; am < 2; am++)
                #pragma unroll
                for (int sub = 0; sub < 2; sub++) {
                    float* a = acc[am][bn * 2 + sub];
                    mma_bf16(a, ah[am], &bh[sub * 2]);
                    mma_bf16(a, ah[am], &bl[sub * 2]);
                    mma_bf16(a, al[am], &bh[sub * 2]);
                }
        }
    }

    float* C = g_S + ((size_t)z * 2048 + m0) * 2048 + n0;
    #pragma unroll
    for (int am = 0; am < 2; am++) {
        int r0 = mw + am * 16 + gid;
        #pragma unroll
        for (int an = 0; an < 8; an++) {
            int gc = nw + an * 8 + tg * 2;
            float* a = acc[am][an];
            *(float2*)(C + (size_t)r0 * 2048 + gc) = make_float2(a[0], a[1]);
            *(float2*)(C + (size_t)(r0 + 8) * 2048 + gc) = make_float2(a[2], a[3]);
        }
    }
}

// ---------------------------------------------------------------------------
__global__ void __launch_bounds__(256) softmax_kernel() {
    int q = blockIdx.x, h = blockIdx.y, b = blockIdx.z;
    float lam = g_lambda;
    const float* s1 = g_S + ((size_t)(b * 16 + 2 * h)) * Nq * Nq + (size_t)q * Nq;
    const float* s2 = s1 + (size_t)Nq * Nq;
    __nv_bfloat16* wh = g_Wh + ((size_t)(b * 8 + h) * 2048 + q) * 2048;
    __nv_bfloat16* wl = g_Wl + ((size_t)(b * 8 + h) * 2048 + q) * 2048;

    int tid = threadIdx.x;
    int base = tid * 8;
    float v1[8], v2[8], m1 = -1e30f, m2 = -1e30f;
    float4 a0 = *(const float4*)(s1 + base), a1 = *(const float4*)(s1 + base + 4);
    float4 b0 = *(const float4*)(s2 + base), b1 = *(const float4*)(s2 + base + 4);
    v1[0] = a0.x; v1[1] = a0.y; v1[2] = a0.z; v1[3] = a0.w;
    v1[4] = a1.x; v1[5] = a1.y; v1[6] = a1.z; v1[7] = a1.w;
    v2[0] = b0.x; v2[1] = b0.y; v2[2] = b0.z; v2[3] = b0.w;
    v2[4] = b1.x; v2[5] = b1.y; v2[6] = b1.z; v2[7] = b1.w;
    #pragma unroll
    for (int i = 0; i < 8; i++) { m1 = fmaxf(m1, v1[i]); m2 = fmaxf(m2, v2[i]); }

    __shared__ float red1[8], red2[8], su1[8], su2[8];
    #pragma unroll
    for (int o = 16; o; o >>= 1) {
        m1 = fmaxf(m1, __shfl_xor_sync(0xFFFFFFFFu, m1, o));
        m2 = fmaxf(m2, __shfl_xor_sync(0xFFFFFFFFu, m2, o));
    }
    int warp = tid >> 5, lane = tid & 31;
    if (lane == 0) { red1[warp] = m1; red2[warp] = m2; }
    __syncthreads();
    m1 = red1[0]; m2 = red2[0];
    #pragma unroll
    for (int w = 1; w < 8; w++) { m1 = fmaxf(m1, red1[w]); m2 = fmaxf(m2, red2[w]); }
    float l1 = 0.f, l2 = 0.f;
    #pragma unroll
    for (int i = 0; i < 8; i++) {
        v1[i] = __expf(v1[i] - m1); l1 += v1[i];
        v2[i] = __expf(v2[i] - m2); l2 += v2[i];
    }
    #pragma unroll
    for (int o = 16; o; o >>= 1) {
        l1 += __shfl_xor_sync(0xFFFFFFFFu, l1, o);
        l2 += __shfl_xor_sync(0xFFFFFFFFu, l2, o);
    }
    if (lane == 0) { su1[warp] = l1; su2[warp] = l2; }
    __syncthreads();
    l1 = su1[0]; l2 = su2[0];
    #pragma unroll
    for (int w = 1; w < 8; w++) { l1 += su1[w]; l2 += su2[w]; }
    float inv1 = 1.f / l1, inv2 = lam / l2;

    uint32_t hp[4], lp[4];
    #pragma unroll
    for (int i = 0; i < 4; i++) {
        float w0 = v1[2 * i] * inv1 - v2[2 * i] * inv2;
        float w1 = v1[2 * i + 1] * inv1 - v2[2 * i + 1] * inv2;
        split2(w0, w1, hp[i], lp[i]);
    }
    *(uint4*)(wh + base) = make_uint4(hp[0], hp[1], hp[2], hp[3]);
    *(uint4*)(wl + base) = make_uint4(lp[0], lp[1], lp[2], lp[3]);
}

// ---------------------------------------------------------------------------
#define PSTG 24576
__global__ void __launch_bounds__(256, 2) gemm_pv(const float* __restrict__ lng,
                                                  const float* __restrict__ lnb) {
    extern __shared__ __align__(1024) char sm[];
    const int tid = threadIdx.x, wid = tid >> 5, lane = tid & 31;
    const int gid = lane >> 2, tg = lane & 3;
    uint32_t t0 = (smem_to_u32(sm) + 1023) & ~1023u;

    int z = blockIdx.z, b = z >> 3, h = z & 7, m0 = blockIdx.y * 64;
    const __nv_bfloat16* Agh = g_Wh + ((size_t)z * 2048 + m0) * 2048;
    const __nv_bfloat16* Agl = g_Wl + ((size_t)z * 2048 + m0) * 2048;
    const __nv_bfloat16* Bgh = g_vth + (size_t)z * 128 * 2048;
    const __nv_bfloat16* Bgl = g_vtl + (size_t)z * 128 * 2048;

    const int mw = (wid >> 1) * 16, nw = (wid & 1) * 64;
    float acc[8][4];
    #pragma unroll
    for (int j = 0; j < 8; j++)
        #pragma unroll
        for (int r = 0; r < 4; r++) acc[j][r] = 0.f;

    auto issue = [&](int st, int c) {
        uint32_t s = t0 + st * PSTG;
        cp_tile32<64>(s,          Agh + c * 32, 2048, tid);
        cp_tile32<64>(s + 4096,   Agl + c * 32, 2048, tid);
        cp_tile32<128>(s + 8192,  Bgh + c * 32, 2048, tid);
        cp_tile32<128>(s + 16384, Bgl + c * 32, 2048, tid);
        CP_COMMIT();
    };
    const int NC = 64;
    issue(0, 0);
    issue(1, 1);
    #pragma unroll 1
    for (int c = 0; c < NC; c++) {
        if (c + 2 < NC) { issue((c + 2) % 3, c + 2); CP_WAIT(2); }
        else if (c == NC - 2) CP_WAIT(1);
        else CP_WAIT(0);
        __syncthreads();
        uint32_t s = t0 + (c % 3) * PSTG;
        uint32_t Ah = s, Al = s + 4096, Bh = s + 8192, Bl = s + 16384;
        #pragma unroll
        for (int ks = 0; ks < 2; ks++) {
            int kb = ks * 32;
            uint32_t ah[4], al[4];
            ldA<64>(Ah, mw, kb, lane, ah);
            ldA<64>(Al, mw, kb, lane, al);
            #pragma unroll
            for (int bn = 0; bn < 4; bn++) {
                uint32_t bh[4], bl[4];
                ldB<64>(Bh, nw + bn * 16, kb, lane, bh);
                ldB<64>(Bl, nw + bn * 16, kb, lane, bl);
                #pragma unroll
                for (int sub = 0; sub < 2; sub++) {
                    float* a = acc[bn * 2 + sub];
                    mma_bf16(a, ah, &bh[sub * 2]);
                    mma_bf16(a, ah, &bl[sub * 2]);
                    mma_bf16(a, al, &bh[sub * 2]);
                }
            }
        }
        __syncthreads();
    }

    float* stg = (float*)(sm + (t0 - smem_to_u32(sm)));
    const int LD = 132;
    #pragma unroll
    for (int an = 0; an < 8; an++) {
        int col = nw + an * 8 + tg * 2;
        stg[(mw + gid) * LD + col] = acc[an][0];
        stg[(mw + gid) * LD + col + 1] = acc[an][1];
        stg[(mw + gid + 8) * LD + col] = acc[an][2];
        stg[(mw + gid + 8) * LD + col + 1] = acc[an][3];
    }
    __syncthreads();

    #pragma unroll 1
    for (int rr = 0; rr < 8; rr++) {
        int r = wid * 8 + rr;
        float x0 = stg[r * LD + lane], x1 = stg[r * LD + lane + 32];
        float x2 = stg[r * LD + lane + 64], x3 = stg[r * LD + lane + 96];
        float s = x0 + x1 + x2 + x3;
        float ss = x0 * x0 + x1 * x1 + x2 * x2 + x3 * x3;
        #pragma unroll
        for (int o = 16; o; o >>= 1) {
            s  += __shfl_xor_sync(0xFFFFFFFFu, s, o);
            ss += __shfl_xor_sync(0xFFFFFFFFu, ss, o);
        }
        float mean = s * (1.f / 128.f);
        float var = ss * (1.f / 128.f) - mean * mean;
        float rstd = rsqrtf(var + 1e-5f);
        size_t base = ((size_t)(b * 2048 + m0 + r)) * 1024 + h * 128;
        float xv[4] = {x0, x1, x2, x3};
        #pragma unroll
        for (int j = 0; j < 4; j++) {
            int c = lane + 32 * j;
            float w = (xv[j] - mean) * rstd * lng[c] + lnb[c];
            __nv_bfloat16 hi = __float2bfloat16(w);
            __nv_bfloat16 lo = __float2bfloat16(w - __bfloat162float(hi));
            g_oh[base + c] = hi;
            g_ol[base + c] = lo;
        }
    }
}

// ---------------------------------------------------------------------------
extern "C" void kernel_launch(void* const* d_in, const int* in_sizes, int n_in,
                              void* d_out, int out_size) {
    const float* x   = (const float*)d_in[0];
    const float* Wq  = (const float*)d_in[1];
    const float* Wk  = (const float*)d_in[2];
    const float* Wv  = (const float*)d_in[3];
    const float* Wo  = (const float*)d_in[4];
    const float* lq1 = (const float*)d_in[5];
    const float* lk1 = (const float*)d_in[6];
    const float* lq2 = (const float*)d_in[7];
    const float* lk2 = (const float*)d_in[8];
    const float* lng = (const float*)d_in[9];
    const float* lnb = (const float*)d_in[10];
    float* out = (float*)d_out;

    const int SM_BIG = 3 * BSTG + 1024;   // 99328  -> 2 CTAs/SM
    const int SM_SC  = 65536 + 1024;      // 66560  -> 2 CTAs/SM
    const int SM_PV  = 3 * PSTG + 1024;   // 74752  -> 2 CTAs/SM
    cudaFuncSetAttribute(gemm_big, cudaFuncAttributeMaxDynamicSharedMemorySize, SM_BIG);
    cudaFuncSetAttribute(gemm_scores, cudaFuncAttributeMaxDynamicSharedMemorySize, SM_SC);
    cudaFuncSetAttribute(gemm_pv, cudaFuncAttributeMaxDynamicSharedMemorySize, SM_PV);

    lambda_kernel<<<1, 32>>>(lq1, lk1, lq2, lk2);
    convert_x<<<4096, 256>>>(x);
    transpose_w<<<dim3(32, 32, 4), dim3(32, 8)>>>(Wq, Wk, Wv, Wo);

    gemm_big<<<dim3(8, 32, 3), 256, SM_BIG>>>(-1, nullptr);   // q,k,v projections
    vtrans_kernel<<<dim3(64, 4, 16), dim3(32, 8)>>>();
    gemm_scores<<<dim3(16, 16, 32), 256, SM_SC>>>();
    softmax_kernel<<<dim3(2048, 8, 2), 256>>>();
    gemm_pv<<<dim3(1, 32, 16), 256, SM_PV>>>(lng, lnb);
    gemm_big<<<dim3(8, 32, 1), 256, SM_BIG>>>(3, out);        // output projection
}